// round 14
// baseline (speedup 1.0000x reference)
#include <cuda_runtime.h>
#include <cuda_fp16.h>
#include <cstdint>

#define BB 4
#define SS 1024
#define DD 256
#define HH 8
#define HDIM 32
#define D3 768
#define MLPD 1024
#define NROWS (BB*SS)   // 4096

// ---------------- scratch (device globals; no allocation allowed) ----------------
__device__ float g_x  [NROWS * DD];    // fp32 activations (residual stream)
__device__ __align__(16) __half g_xh  [NROWS * DD];    // activations hi
__device__ __align__(16) __half g_xl  [NROWS * DD];    // activations lo
__device__ __align__(16) __half g_qkvh[NROWS * D3];    // qkv hi
__device__ __align__(16) __half g_qkvl[NROWS * D3];    // qkv lo
__device__ __align__(16) __half g_aoh [NROWS * DD];    // attention out hi
__device__ __align__(16) __half g_aol [NROWS * DD];    // attention out lo
__device__ __align__(16) __half g_hh  [NROWS * MLPD];  // MLP hidden hi
__device__ __align__(16) __half g_hl  [NROWS * MLPD];  // MLP hidden lo
// split-K attention partials (2 splits)
__device__ float g_po[2 * NROWS * DD];   // unnormalized partial O
__device__ float g_pm[2 * NROWS * HH];   // row max
__device__ float g_pl[2 * NROWS * HH];   // row sum
// split weights (converted once per call)
__device__ __align__(16) __half g_wina_h [2 * D3 * DD],   g_wina_l [2 * D3 * DD];
__device__ __align__(16) __half g_wouta_h[2 * DD * DD],   g_wouta_l[2 * DD * DD];
__device__ __align__(16) __half g_wine_h [2 * D3 * DD],   g_wine_l [2 * D3 * DD];
__device__ __align__(16) __half g_woute_h[2 * DD * DD],   g_woute_l[2 * DD * DD];
__device__ __align__(16) __half g_w1_h   [2 * MLPD * DD], g_w1_l   [2 * MLPD * DD];
__device__ __align__(16) __half g_w2_h   [2 * DD * MLPD], g_w2_l   [2 * DD * MLPD];

// ---------------- helpers ----------------
__device__ __forceinline__ void cp16(uint32_t dst, const void* src) {
    asm volatile("cp.async.cg.shared.global [%0], [%1], 16;" :: "r"(dst), "l"(src));
}
__device__ __forceinline__ void cp_commit() { asm volatile("cp.async.commit_group;"); }
template <int N> __device__ __forceinline__ void cp_wait() {
    asm volatile("cp.async.wait_group %0;" :: "n"(N));
}
#define LDMX4(r0, r1, r2, r3, addr) \
    asm volatile("ldmatrix.sync.aligned.m8n8.x4.shared.b16 {%0,%1,%2,%3}, [%4];" \
        : "=r"(r0), "=r"(r1), "=r"(r2), "=r"(r3) : "r"(addr))
#define LDMX4T(r0, r1, r2, r3, addr) \
    asm volatile("ldmatrix.sync.aligned.m8n8.x4.trans.shared.b16 {%0,%1,%2,%3}, [%4];" \
        : "=r"(r0), "=r"(r1), "=r"(r2), "=r"(r3) : "r"(addr))
#define MMA16816(d, a, b) \
    asm volatile("mma.sync.aligned.m16n8k16.row.col.f32.f16.f16.f32 " \
        "{%0,%1,%2,%3}, {%4,%5,%6,%7}, {%8,%9}, {%0,%1,%2,%3};" \
        : "+f"(d[0]), "+f"(d[1]), "+f"(d[2]), "+f"(d[3]) \
        : "r"(a[0]), "r"(a[1]), "r"(a[2]), "r"(a[3]), "r"(b[0]), "r"(b[1]))

__device__ __forceinline__ void split2(float v, __half& hi, __half& lo) {
    hi = __float2half(v);
    lo = __float2half(v - __half2float(hi));
}
__device__ __forceinline__ uint32_t packh2(__half a, __half b) {
    __half2 h = __halves2half2(a, b);
    return *(uint32_t*)&h;
}
// swizzled offset (halfs) of the 8-half chunk (row r, chunk ck in 0..3) of a 64x32-half tile
__device__ __forceinline__ int swoff(int r, int ck) {
    return (r >> 1) * 64 + (((((r & 1) << 2) | ck) ^ ((r >> 1) & 7)) << 3);
}

// ---------------- merged fp32 -> (hi, lo) fp16 pair conversion ----------------
struct CvtArgs {
    const float* s[6];
    __half* h[6];
    __half* l[6];
    int off[7];
};
__global__ void f2h2all_kernel(CvtArgs a) {
    int i = blockIdx.x * blockDim.x + threadIdx.x;
    if (i >= a.off[6]) return;
    int seg = 0;
#pragma unroll
    for (int s = 1; s < 6; s++) if (i >= a.off[s]) seg = s;
    int j = i - a.off[seg];
    __half h, l; split2(a.s[seg][j], h, l);
    a.h[seg][j] = h; a.l[seg][j] = l;
}

// ---------------- pos add ----------------
__global__ void posadd_kernel(const float* __restrict__ xin, const float* __restrict__ scale,
                              float* __restrict__ out, __half* __restrict__ oh,
                              __half* __restrict__ ol) {
    int row = blockIdx.x;
    int d = threadIdx.x;
    int s = row & (SS - 1);
    float v = xin[row * DD + d] + (float)s * scale[0];
    out[row * DD + d] = v;
    __half h, l; split2(v, h, l);
    oh[row * DD + d] = h; ol[row * DD + d] = l;
}

// ---------------- standalone layernorm (final LN only) ----------------
__global__ void ln_kernel(const float* __restrict__ in, const float* __restrict__ gam,
                          const float* __restrict__ bet, float* __restrict__ out) {
    int row = blockIdx.x;
    int tid = threadIdx.x;
    __shared__ float red[256];
    float v = in[row * DD + tid];
    red[tid] = v;
    __syncthreads();
    for (int o = 128; o > 0; o >>= 1) {
        if (tid < o) red[tid] += red[tid + o];
        __syncthreads();
    }
    float mean = red[0] * (1.0f / DD);
    __syncthreads();
    float c = v - mean;
    red[tid] = c * c;
    __syncthreads();
    for (int o = 128; o > 0; o >>= 1) {
        if (tid < o) red[tid] += red[tid + o];
        __syncthreads();
    }
    float var = red[0] * (1.0f / DD);
    out[row * DD + tid] = c * rsqrtf(var + 1e-5f) * gam[tid] + bet[tid];
}

// ---------------- split-fp16 tensor-core GEMM: C = act(A @ B^T + bias) (+res) ------
// BM=128, BK=64, 2-stage, 3-term split.
template <int BN, int WM_, int WN_, int ACT, int RES, int OUTF, int OUTH>
__global__ void __launch_bounds__(256)
hgemm3_kernel(const __half* __restrict__ Ah, const __half* __restrict__ Al,
              const __half* __restrict__ Bh, const __half* __restrict__ Bl,
              const float* __restrict__ bias, const float* __restrict__ res,
              float* __restrict__ C, __half* __restrict__ Chh, __half* __restrict__ Chl,
              int M, int N, int K) {
    constexpr int BM = 128, BK = 64;
    constexpr int MITER = BM / (WM_ * 16);
    constexpr int NITER = BN / (WN_ * 8);
    constexpr int ASZ = BM * BK, BSZ = BN * BK;
    constexpr int SSZ = 2 * ASZ + 2 * BSZ;   // halfs per stage: Ah|Al|Bh|Bl

    extern __shared__ __half smh[];
    const int tid = threadIdx.x;
    const int lane = tid & 31, warp = tid >> 5;
    const int wm = warp / WN_, wn = warp % WN_;
    const int m0 = blockIdx.y * BM, n0 = blockIdx.x * BN;
    const uint32_t sbase = (uint32_t)__cvta_generic_to_shared(smh);
    const int nt = K / BK;

    auto load_tile = [&](int stg, int kt) {
        uint32_t s0 = sbase + (uint32_t)(stg * SSZ) * 2u;
#pragma unroll
        for (int i = 0; i < BM * 8 / 256; i++) {
            int c = tid + i * 256;
            int r = c >> 3, ck = c & 7;
            uint32_t off = (uint32_t)(r * BK + ((ck ^ (r & 7)) << 3)) * 2u;
            const size_t gi = (size_t)(m0 + r) * K + kt * BK + ck * 8;
            cp16(s0 + off, Ah + gi);
            cp16(s0 + (uint32_t)ASZ * 2u + off, Al + gi);
        }
#pragma unroll
        for (int i = 0; i < BN * 8 / 256; i++) {
            int c = tid + i * 256;
            int r = c >> 3, ck = c & 7;
            uint32_t off = (uint32_t)(r * BK + ((ck ^ (r & 7)) << 3)) * 2u;
            const size_t gi = (size_t)(n0 + r) * K + kt * BK + ck * 8;
            cp16(s0 + (uint32_t)(2 * ASZ) * 2u + off, Bh + gi);
            cp16(s0 + (uint32_t)(2 * ASZ + BSZ) * 2u + off, Bl + gi);
        }
    };

    float acc[MITER][NITER][4];
#pragma unroll
    for (int i = 0; i < MITER; i++)
#pragma unroll
        for (int j = 0; j < NITER; j++)
#pragma unroll
            for (int q = 0; q < 4; q++) acc[i][j][q] = 0.0f;

    load_tile(0, 0);
    cp_commit();

    for (int t = 0; t < nt; t++) {
        cp_wait<0>();
        __syncthreads();
        if (t + 1 < nt) load_tile((t + 1) & 1, t + 1);
        cp_commit();

        int stg = t & 1;
        uint32_t ahb = sbase + (uint32_t)(stg * SSZ) * 2u;
        uint32_t alb = ahb + (uint32_t)ASZ * 2u;
        uint32_t bhb = ahb + (uint32_t)(2 * ASZ) * 2u;
        uint32_t blb = ahb + (uint32_t)(2 * ASZ + BSZ) * 2u;
#pragma unroll
        for (int ks = 0; ks < BK / 16; ks++) {
            uint32_t ah[MITER][4], al[MITER][4];
            uint32_t bh[NITER][2], bl[NITER][2];
#pragma unroll
            for (int i = 0; i < MITER; i++) {
                int r = wm * MITER * 16 + i * 16 + (lane & 15);
                int ck = ks * 2 + (lane >> 4);
                uint32_t off = (uint32_t)(r * BK + ((ck ^ (r & 7)) << 3)) * 2u;
                LDMX4(ah[i][0], ah[i][1], ah[i][2], ah[i][3], ahb + off);
                LDMX4(al[i][0], al[i][1], al[i][2], al[i][3], alb + off);
            }
#pragma unroll
            for (int j = 0; j < NITER / 2; j++) {
                int r = wn * NITER * 8 + j * 16 + (lane & 7) + ((lane >> 4) << 3);
                int ck = ks * 2 + ((lane >> 3) & 1);
                uint32_t off = (uint32_t)(r * BK + ((ck ^ (r & 7)) << 3)) * 2u;
                LDMX4(bh[2 * j][0], bh[2 * j][1], bh[2 * j + 1][0], bh[2 * j + 1][1], bhb + off);
                LDMX4(bl[2 * j][0], bl[2 * j][1], bl[2 * j + 1][0], bl[2 * j + 1][1], blb + off);
            }
#pragma unroll
            for (int i = 0; i < MITER; i++)
#pragma unroll
                for (int j = 0; j < NITER; j++) {
                    MMA16816(acc[i][j], ah[i], bh[j]);
                    MMA16816(acc[i][j], al[i], bh[j]);
                    MMA16816(acc[i][j], ah[i], bl[j]);
                }
        }
        __syncthreads();
    }

    // epilogue
#pragma unroll
    for (int i = 0; i < MITER; i++) {
#pragma unroll
        for (int j = 0; j < NITER; j++) {
            int m = m0 + wm * MITER * 16 + i * 16 + (lane >> 2);
            int n = n0 + wn * NITER * 8 + j * 8 + (lane & 3) * 2;
            float2 bb = *(const float2*)(bias + n);
            float v0 = acc[i][j][0] + bb.x;
            float v1 = acc[i][j][1] + bb.y;
            float v2 = acc[i][j][2] + bb.x;
            float v3 = acc[i][j][3] + bb.y;
            if (ACT) {
                v0 = 0.5f * v0 * (1.0f + erff(v0 * 0.70710678118654752f));
                v1 = 0.5f * v1 * (1.0f + erff(v1 * 0.70710678118654752f));
                v2 = 0.5f * v2 * (1.0f + erff(v2 * 0.70710678118654752f));
                v3 = 0.5f * v3 * (1.0f + erff(v3 * 0.70710678118654752f));
            }
            if (RES) {
                float2 r0 = *(const float2*)(res + (size_t)m * N + n);
                float2 r1 = *(const float2*)(res + (size_t)(m + 8) * N + n);
                v0 += r0.x; v1 += r0.y; v2 += r1.x; v3 += r1.y;
            }
            if (OUTF) {
                *(float2*)(C + (size_t)m * N + n) = make_float2(v0, v1);
                *(float2*)(C + (size_t)(m + 8) * N + n) = make_float2(v2, v3);
            }
            if (OUTH) {
                __half h0, l0, h1, l1, h2, l2, h3, l3;
                split2(v0, h0, l0); split2(v1, h1, l1);
                split2(v2, h2, l2); split2(v3, h3, l3);
                *(__half2*)(Chh + (size_t)m * N + n)       = __halves2half2(h0, h1);
                *(__half2*)(Chh + (size_t)(m + 8) * N + n) = __halves2half2(h2, h3);
                *(__half2*)(Chl + (size_t)m * N + n)       = __halves2half2(l0, l1);
                *(__half2*)(Chl + (size_t)(m + 8) * N + n) = __halves2half2(l2, l3);
            }
        }
    }
}

// ---------------- fused out-proj GEMM + residual + LayerNorm (split fp16) ----------
__global__ void __launch_bounds__(256)
gemmln_kernel(const __half* __restrict__ Ah, const __half* __restrict__ Al,
              const __half* __restrict__ Bh, const __half* __restrict__ Bl,
              const float* __restrict__ bias, const float* __restrict__ res,
              const float* __restrict__ gam, const float* __restrict__ bet,
              float* __restrict__ X, __half* __restrict__ Xh, __half* __restrict__ Xl) {
    constexpr int BM = 32, BN = 256, BK = 64, K = 256, N = 256;
    constexpr int NITER = 8;
    constexpr int ASZ = BM * BK, BSZ = BN * BK;
    constexpr int SSZ = 2 * ASZ + 2 * BSZ;
    constexpr int nt = K / BK;

    extern __shared__ __half smh[];
    __shared__ float ps[32][4], pq[32][4];
    const int tid = threadIdx.x;
    const int lane = tid & 31, warp = tid >> 5;
    const int wm = warp >> 2, wn = warp & 3;
    const int g = lane >> 2, t = lane & 3;
    const int m0 = blockIdx.x * BM;
    const uint32_t sbase = (uint32_t)__cvta_generic_to_shared(smh);

    auto load_tile = [&](int stg, int kt) {
        uint32_t s0 = sbase + (uint32_t)(stg * SSZ) * 2u;
        {
            int r = tid >> 3, ck = tid & 7;
            uint32_t off = (uint32_t)(r * BK + ((ck ^ (r & 7)) << 3)) * 2u;
            const size_t gi = (size_t)(m0 + r) * K + kt * BK + ck * 8;
            cp16(s0 + off, Ah + gi);
            cp16(s0 + (uint32_t)ASZ * 2u + off, Al + gi);
        }
#pragma unroll
        for (int i = 0; i < 8; i++) {
            int c = tid + i * 256;
            int r = c >> 3, ck = c & 7;
            uint32_t off = (uint32_t)(r * BK + ((ck ^ (r & 7)) << 3)) * 2u;
            const size_t gi = (size_t)r * K + kt * BK + ck * 8;
            cp16(s0 + (uint32_t)(2 * ASZ) * 2u + off, Bh + gi);
            cp16(s0 + (uint32_t)(2 * ASZ + BSZ) * 2u + off, Bl + gi);
        }
    };

    float acc[NITER][4];
#pragma unroll
    for (int j = 0; j < NITER; j++)
#pragma unroll
        for (int q = 0; q < 4; q++) acc[j][q] = 0.0f;

    load_tile(0, 0);
    cp_commit();

    for (int tt = 0; tt < nt; tt++) {
        cp_wait<0>();
        __syncthreads();
        if (tt + 1 < nt) load_tile((tt + 1) & 1, tt + 1);
        cp_commit();

        int stg = tt & 1;
        uint32_t ahb = sbase + (uint32_t)(stg * SSZ) * 2u;
        uint32_t alb = ahb + (uint32_t)ASZ * 2u;
        uint32_t bhb = ahb + (uint32_t)(2 * ASZ) * 2u;
        uint32_t blb = ahb + (uint32_t)(2 * ASZ + BSZ) * 2u;
#pragma unroll
        for (int ks = 0; ks < BK / 16; ks++) {
            uint32_t ah[4], al[4];
            {
                int r = wm * 16 + (lane & 15);
                int ck = ks * 2 + (lane >> 4);
                uint32_t off = (uint32_t)(r * BK + ((ck ^ (r & 7)) << 3)) * 2u;
                LDMX4(ah[0], ah[1], ah[2], ah[3], ahb + off);
                LDMX4(al[0], al[1], al[2], al[3], alb + off);
            }
            uint32_t bh[NITER][2], bl[NITER][2];
#pragma unroll
            for (int j = 0; j < NITER / 2; j++) {
                int r = wn * 64 + j * 16 + (lane & 7) + ((lane >> 4) << 3);
                int ck = ks * 2 + ((lane >> 3) & 1);
                uint32_t off = (uint32_t)(r * BK + ((ck ^ (r & 7)) << 3)) * 2u;
                LDMX4(bh[2 * j][0], bh[2 * j][1], bh[2 * j + 1][0], bh[2 * j + 1][1], bhb + off);
                LDMX4(bl[2 * j][0], bl[2 * j][1], bl[2 * j + 1][0], bl[2 * j + 1][1], blb + off);
            }
#pragma unroll
            for (int j = 0; j < NITER; j++) {
                MMA16816(acc[j], ah, bh[j]);
                MMA16816(acc[j], al, bh[j]);
                MMA16816(acc[j], ah, bl[j]);
            }
        }
        __syncthreads();
    }

    const int lrA = wm * 16 + g;
    const int lrB = lrA + 8;
    const int mA = m0 + lrA, mB = m0 + lrB;

    float sA = 0.0f, qA = 0.0f, sB = 0.0f, qB = 0.0f;
#pragma unroll
    for (int j = 0; j < NITER; j++) {
        int n = wn * 64 + j * 8 + t * 2;
        float2 bb = *(const float2*)(bias + n);
        float2 r0 = *(const float2*)(res + (size_t)mA * N + n);
        float2 r1 = *(const float2*)(res + (size_t)mB * N + n);
        float v0 = acc[j][0] + bb.x + r0.x;
        float v1 = acc[j][1] + bb.y + r0.y;
        float v2 = acc[j][2] + bb.x + r1.x;
        float v3 = acc[j][3] + bb.y + r1.y;
        acc[j][0] = v0; acc[j][1] = v1; acc[j][2] = v2; acc[j][3] = v3;
        sA += v0 + v1; qA += v0 * v0 + v1 * v1;
        sB += v2 + v3; qB += v2 * v2 + v3 * v3;
    }
    sA += __shfl_xor_sync(0xffffffffu, sA, 1); sA += __shfl_xor_sync(0xffffffffu, sA, 2);
    qA += __shfl_xor_sync(0xffffffffu, qA, 1); qA += __shfl_xor_sync(0xffffffffu, qA, 2);
    sB += __shfl_xor_sync(0xffffffffu, sB, 1); sB += __shfl_xor_sync(0xffffffffu, sB, 2);
    qB += __shfl_xor_sync(0xffffffffu, qB, 1); qB += __shfl_xor_sync(0xffffffffu, qB, 2);
    if (t == 0) { ps[lrA][wn] = sA; pq[lrA][wn] = qA; ps[lrB][wn] = sB; pq[lrB][wn] = qB; }
    __syncthreads();

    float sumA = ps[lrA][0] + ps[lrA][1] + ps[lrA][2] + ps[lrA][3];
    float sqA  = pq[lrA][0] + pq[lrA][1] + pq[lrA][2] + pq[lrA][3];
    float sumB = ps[lrB][0] + ps[lrB][1] + ps[lrB][2] + ps[lrB][3];
    float sqB  = pq[lrB][0] + pq[lrB][1] + pq[lrB][2] + pq[lrB][3];
    float meanA = sumA * (1.0f / N), meanB = sumB * (1.0f / N);
    float varA = sqA * (1.0f / N) - meanA * meanA;
    float varB = sqB * (1.0f / N) - meanB * meanB;
    float rA = rsqrtf(varA + 1e-5f), rB = rsqrtf(varB + 1e-5f);

#pragma unroll
    for (int j = 0; j < NITER; j++) {
        int n = wn * 64 + j * 8 + t * 2;
        float2 gg = *(const float2*)(gam + n);
        float2 be = *(const float2*)(bet + n);
        float y0 = (acc[j][0] - meanA) * rA * gg.x + be.x;
        float y1 = (acc[j][1] - meanA) * rA * gg.y + be.y;
        float y2 = (acc[j][2] - meanB) * rB * gg.x + be.x;
        float y3 = (acc[j][3] - meanB) * rB * gg.y + be.y;
        *(float2*)(X + (size_t)mA * N + n) = make_float2(y0, y1);
        *(float2*)(X + (size_t)mB * N + n) = make_float2(y2, y3);
        __half h0, l0, h1, l1, h2, l2, h3, l3;
        split2(y0, h0, l0); split2(y1, h1, l1);
        split2(y2, h2, l2); split2(y3, h3, l3);
        *(__half2*)(Xh + (size_t)mA * N + n) = __halves2half2(h0, h1);
        *(__half2*)(Xl + (size_t)mA * N + n) = __halves2half2(l0, l1);
        *(__half2*)(Xh + (size_t)mB * N + n) = __halves2half2(h2, h3);
        *(__half2*)(Xl + (size_t)mB * N + n) = __halves2half2(l2, l3);
    }
}

// ---------------- tensor-core flash attention (split fp16, fp32 softmax) ----------------
// 128 threads, 64 q-rows per block. P-split fused with PV per 16-row k-group to cut
// register live ranges; occupancy forced to 5 blocks/SM.
template <int BANDED, int SPLITK>
__global__ void __launch_bounds__(128, 5)
attn2_kernel(const __half* __restrict__ qh, const __half* __restrict__ ql,
             __half* __restrict__ aoh, __half* __restrict__ aol,
             float* __restrict__ po, float* __restrict__ pm, float* __restrict__ pl) {
    __shared__ __half sm[20480];
    int qt, sp = 0;
    if (SPLITK) { qt = blockIdx.x >> 1; sp = blockIdx.x & 1; }
    else        { qt = blockIdx.x; }
    const int h = blockIdx.y, b = blockIdx.z;
    const int q0 = qt * 64;
    const int tid = threadIdx.x;
    const int lane = tid & 31, w = tid >> 5;
    const int g = lane >> 2, t = lane & 3;
    const uint32_t sb = (uint32_t)__cvta_generic_to_shared(sm);

#pragma unroll
    for (int i = 0; i < 4; i++) {
        int idx = tid + i * 128;
        int matl = idx >> 8;
        int c = idx & 255;
        int r = c >> 2, ck = c & 3;
        const __half* src = (matl ? ql : qh) + (size_t)(b * SS + q0 + r) * D3 + h * HDIM + ck * 8;
        cp16(sb + (uint32_t)(matl * 2048 + swoff(r, ck)) * 2u, src);
    }

    int jt0, jt1;
    if (SPLITK)      { jt0 = sp * 8; jt1 = jt0 + 7; }
    else if (BANDED) { jt0 = max(0, qt - 1); jt1 = min(SS / 64 - 1, qt + 1); }
    else             { jt0 = 0; jt1 = SS / 64 - 1; }

    auto stage_kv = [&](int buf, int jt) {
        int j0 = jt * 64;
#pragma unroll
        for (int i = 0; i < 8; i++) {
            int idx = tid + i * 128;
            int mat = idx >> 8;
            int c = idx & 255;
            int r = c >> 2, ck = c & 3;
            int sec = (mat >> 1) ? 2 * DD : DD;
            const __half* src = ((mat & 1) ? ql : qh)
                + (size_t)(b * SS + j0 + r) * D3 + sec + h * HDIM + ck * 8;
            cp16(sb + (uint32_t)(4096 + buf * 8192 + mat * 2048 + swoff(r, ck)) * 2u, src);
        }
    };

    stage_kv(0, jt0);
    cp_commit();
    cp_wait<0>();
    __syncthreads();

    uint32_t ah[2][4], al[2][4];
    {
        int r = w * 16 + (lane & 15);
#pragma unroll
        for (int kb = 0; kb < 2; kb++) {
            int ck = kb * 2 + (lane >> 4);
            uint32_t off = (uint32_t)swoff(r, ck) * 2u;
            LDMX4(ah[kb][0], ah[kb][1], ah[kb][2], ah[kb][3], sb + off);
            LDMX4(al[kb][0], al[kb][1], al[kb][2], al[kb][3], sb + 4096u + off);
        }
    }

    float o[4][4];
#pragma unroll
    for (int dn = 0; dn < 4; dn++)
#pragma unroll
        for (int q = 0; q < 4; q++) o[dn][q] = 0.0f;
    float mA = -1e30f, mB = -1e30f, lA = 0.0f, lB = 0.0f;
    const float scl = 0.17677669529663687f;

    for (int jt = jt0; jt <= jt1; jt++) {
        int buf = (jt - jt0) & 1;
        if (jt < jt1) { stage_kv(buf ^ 1, jt + 1); cp_commit(); }
        uint32_t kvb = sb + (uint32_t)(4096 + buf * 8192) * 2u;

        float accs[8][4];
#pragma unroll
        for (int j = 0; j < 8; j++)
#pragma unroll
            for (int q = 0; q < 4; q++) accs[j][q] = 0.0f;
#pragma unroll
        for (int kb = 0; kb < 2; kb++) {
#pragma unroll
            for (int jg = 0; jg < 4; jg++) {
                int r = jg * 16 + (lane & 7) + ((lane >> 4) << 3);
                int ck = kb * 2 + ((lane >> 3) & 1);
                uint32_t off = (uint32_t)swoff(r, ck) * 2u;
                uint32_t kh[4], kl[4];
                LDMX4(kh[0], kh[1], kh[2], kh[3], kvb + off);
                LDMX4(kl[0], kl[1], kl[2], kl[3], kvb + 4096u + off);
                uint32_t b0h[2] = {kh[0], kh[1]}, b1h[2] = {kh[2], kh[3]};
                uint32_t b0l[2] = {kl[0], kl[1]}, b1l[2] = {kl[2], kl[3]};
                MMA16816(accs[2 * jg],     ah[kb], b0h);
                MMA16816(accs[2 * jg],     al[kb], b0h);
                MMA16816(accs[2 * jg],     ah[kb], b0l);
                MMA16816(accs[2 * jg + 1], ah[kb], b1h);
                MMA16816(accs[2 * jg + 1], al[kb], b1h);
                MMA16816(accs[2 * jg + 1], ah[kb], b1l);
            }
        }

        int j0k = jt * 64;
#pragma unroll
        for (int j = 0; j < 8; j++)
#pragma unroll
            for (int q = 0; q < 4; q++) {
                float s = accs[j][q] * scl;
                if (BANDED) {
                    int qrow = q0 + w * 16 + g + ((q >> 1) << 3);
                    int kcol = j0k + j * 8 + 2 * t + (q & 1);
                    if (abs(qrow - kcol) > 64) s = -1.0e9f;
                }
                accs[j][q] = s;
            }

        float cmA = -1e30f, cmB = -1e30f;
#pragma unroll
        for (int j = 0; j < 8; j++) {
            cmA = fmaxf(cmA, fmaxf(accs[j][0], accs[j][1]));
            cmB = fmaxf(cmB, fmaxf(accs[j][2], accs[j][3]));
        }
        cmA = fmaxf(cmA, __shfl_xor_sync(0xffffffffu, cmA, 1));
        cmA = fmaxf(cmA, __shfl_xor_sync(0xffffffffu, cmA, 2));
        cmB = fmaxf(cmB, __shfl_xor_sync(0xffffffffu, cmB, 1));
        cmB = fmaxf(cmB, __shfl_xor_sync(0xffffffffu, cmB, 2));
        float nmA = fmaxf(mA, cmA), nmB = fmaxf(mB, cmB);
        float aA = __expf(mA - nmA), aB = __expf(mB - nmB);
        mA = nmA; mB = nmB;
#pragma unroll
        for (int dn = 0; dn < 4; dn++) {
            o[dn][0] *= aA; o[dn][1] *= aA; o[dn][2] *= aB; o[dn][3] *= aB;
        }

        // ---- fused P-split + PV per 16-row k-group (short P live range) ----
        float tsA = 0.0f, tsB = 0.0f;
#pragma unroll
        for (int kk = 0; kk < 4; kk++) {
            uint32_t pah[4], pal[4];
#pragma unroll
            for (int jj = 0; jj < 2; jj++) {
                int j = 2 * kk + jj;
                float p0 = __expf(accs[j][0] - nmA);
                float p1 = __expf(accs[j][1] - nmA);
                float p2 = __expf(accs[j][2] - nmB);
                float p3 = __expf(accs[j][3] - nmB);
                tsA += p0 + p1; tsB += p2 + p3;
                __half h0, l0, h1, l1, h2, l2, h3, l3;
                split2(p0, h0, l0); split2(p1, h1, l1);
                split2(p2, h2, l2); split2(p3, h3, l3);
                pah[0 + 2 * jj] = packh2(h0, h1);
                pah[1 + 2 * jj] = packh2(h2, h3);
                pal[0 + 2 * jj] = packh2(l0, l1);
                pal[1 + 2 * jj] = packh2(l2, l3);
            }
#pragma unroll
            for (int dnp = 0; dnp < 2; dnp++) {
                int r = kk * 16 + ((lane >> 3) & 1) * 8 + (lane & 7);
                int ck = dnp * 2 + (lane >> 4);
                uint32_t off = (uint32_t)swoff(r, ck) * 2u;
                uint32_t vh[4], vl[4];
                LDMX4T(vh[0], vh[1], vh[2], vh[3], kvb + 8192u + off);
                LDMX4T(vl[0], vl[1], vl[2], vl[3], kvb + 12288u + off);
                uint32_t b0h[2] = {vh[0], vh[1]}, b1h[2] = {vh[2], vh[3]};
                uint32_t b0l[2] = {vl[0], vl[1]}, b1l[2] = {vl[2], vl[3]};
                MMA16816(o[2 * dnp],     pah, b0h);
                MMA16816(o[2 * dnp],     pal, b0h);
                MMA16816(o[2 * dnp],     pah, b0l);
                MMA16816(o[2 * dnp + 1], pah, b1h);
                MMA16816(o[2 * dnp + 1], pal, b1h);
                MMA16816(o[2 * dnp + 1], pah, b1l);
            }
        }
        tsA += __shfl_xor_sync(0xffffffffu, tsA, 1);
        tsA += __shfl_xor_sync(0xffffffffu, tsA, 2);
        tsB += __shfl_xor_sync(0xffffffffu, tsB, 1);
        tsB += __shfl_xor_sync(0xffffffffu, tsB, 2);
        lA = lA * aA + tsA;
        lB = lB * aB + tsB;

        if (jt < jt1) cp_wait<0>();
        __syncthreads();
    }

    int rowA = b * SS + q0 + w * 16 + g;
    if (SPLITK) {
        float* poS = po + (size_t)sp * NROWS * DD;
#pragma unroll
        for (int dn = 0; dn < 4; dn++) {
            int col = h * HDIM + dn * 8 + 2 * t;
            *(float2*)(poS + (size_t)rowA * DD + col)       = make_float2(o[dn][0], o[dn][1]);
            *(float2*)(poS + (size_t)(rowA + 8) * DD + col) = make_float2(o[dn][2], o[dn][3]);
        }
        if (t == 0) {
            pm[(size_t)sp * NROWS * HH + rowA * HH + h] = mA;
            pl[(size_t)sp * NROWS * HH + rowA * HH + h] = lA;
            pm[(size_t)sp * NROWS * HH + (rowA + 8) * HH + h] = mB;
            pl[(size_t)sp * NROWS * HH + (rowA + 8) * HH + h] = lB;
        }
    } else {
        float invA = 1.0f / lA, invB = 1.0f / lB;
#pragma unroll
        for (int dn = 0; dn < 4; dn++) {
            int col = h * HDIM + dn * 8 + 2 * t;
            float v0 = o[dn][0] * invA, v1 = o[dn][1] * invA;
            float v2 = o[dn][2] * invB, v3 = o[dn][3] * invB;
            __half h0, l0, h1, l1, h2, l2, h3, l3;
            split2(v0, h0, l0); split2(v1, h1, l1);
            split2(v2, h2, l2); split2(v3, h3, l3);
            *(__half2*)(aoh + (size_t)rowA * DD + col)       = __halves2half2(h0, h1);
            *(__half2*)(aol + (size_t)rowA * DD + col)       = __halves2half2(l0, l1);
            *(__half2*)(aoh + (size_t)(rowA + 8) * DD + col) = __halves2half2(h2, h3);
            *(__half2*)(aol + (size_t)(rowA + 8) * DD + col) = __halves2half2(l2, l3);
        }
    }
}

// ---------------- split-K combine: merge 2 partials with log-sum-exp reweighting ----
__global__ void attncomb_kernel(const float* __restrict__ po, const float* __restrict__ pm,
                                const float* __restrict__ pl,
                                __half* __restrict__ aoh, __half* __restrict__ aol) {
    int row = blockIdx.x;
    int c = threadIdx.x;          // 0..255
    int h = c >> 5;
    float m1 = pm[(size_t)row * HH + h];
    float m2 = pm[(size_t)NROWS * HH + row * HH + h];
    float l1 = pl[(size_t)row * HH + h];
    float l2 = pl[(size_t)NROWS * HH + row * HH + h];
    float mm = fmaxf(m1, m2);
    float w1 = __expf(m1 - mm), w2 = __expf(m2 - mm);
    float o1 = po[(size_t)row * DD + c];
    float o2 = po[(size_t)NROWS * DD + row * DD + c];
    float v = (w1 * o1 + w2 * o2) / (w1 * l1 + w2 * l2);
    __half hi, lo; split2(v, hi, lo);
    aoh[(size_t)row * DD + c] = hi;
    aol[(size_t)row * DD + c] = lo;
}

// ---------------- host launch sequence ----------------
extern "C" void kernel_launch(void* const* d_in, const int* in_sizes, int n_in,
                              void* d_out, int out_size) {
    const float* x_in  = (const float*)d_in[0];
    const float* scale = (const float*)d_in[1];
    const float* Win_a = (const float*)d_in[2];
    const float* bin_a = (const float*)d_in[3];
    const float* Wout_a= (const float*)d_in[4];
    const float* bout_a= (const float*)d_in[5];
    const float* Win_e = (const float*)d_in[6];
    const float* bin_e = (const float*)d_in[7];
    const float* Wout_e= (const float*)d_in[8];
    const float* bout_e= (const float*)d_in[9];
    const float* ln1_g = (const float*)d_in[10];
    const float* ln1_b = (const float*)d_in[11];
    const float* ln2_g = (const float*)d_in[12];
    const float* ln2_b = (const float*)d_in[13];
    const float* W1    = (const float*)d_in[14];
    const float* b1    = (const float*)d_in[15];
    const float* W2    = (const float*)d_in[16];
    const float* b2    = (const float*)d_in[17];
    const float* lnf_g = (const float*)d_in[18];
    const float* lnf_b = (const float*)d_in[19];
    float* out = (float*)d_out;

    float *X, *PO, *PM, *PL;
    __half *Xh, *Xl, *QKVh, *QKVl, *AOh, *AOl, *Hh, *Hl;
    __half *WinaH, *WinaL, *WoutaH, *WoutaL, *WineH, *WineL, *WouteH, *WouteL;
    __half *W1H, *W1L, *W2H, *W2L;
    cudaGetSymbolAddress((void**)&X,   g_x);
    cudaGetSymbolAddress((void**)&PO,  g_po);
    cudaGetSymbolAddress((void**)&PM,  g_pm);
    cudaGetSymbolAddress((void**)&PL,  g_pl);
    cudaGetSymbolAddress((void**)&Xh,  g_xh);    cudaGetSymbolAddress((void**)&Xl,  g_xl);
    cudaGetSymbolAddress((void**)&QKVh, g_qkvh); cudaGetSymbolAddress((void**)&QKVl, g_qkvl);
    cudaGetSymbolAddress((void**)&AOh, g_aoh);   cudaGetSymbolAddress((void**)&AOl, g_aol);
    cudaGetSymbolAddress((void**)&Hh,  g_hh);    cudaGetSymbolAddress((void**)&Hl,  g_hl);
    cudaGetSymbolAddress((void**)&WinaH,  g_wina_h);  cudaGetSymbolAddress((void**)&WinaL,  g_wina_l);
    cudaGetSymbolAddress((void**)&WoutaH, g_wouta_h); cudaGetSymbolAddress((void**)&WoutaL, g_wouta_l);
    cudaGetSymbolAddress((void**)&WineH,  g_wine_h);  cudaGetSymbolAddress((void**)&WineL,  g_wine_l);
    cudaGetSymbolAddress((void**)&WouteH, g_woute_h); cudaGetSymbolAddress((void**)&WouteL, g_woute_l);
    cudaGetSymbolAddress((void**)&W1H,    g_w1_h);    cudaGetSymbolAddress((void**)&W1L,    g_w1_l);
    cudaGetSymbolAddress((void**)&W2H,    g_w2_h);    cudaGetSymbolAddress((void**)&W2L,    g_w2_l);

    const int SM64  = 2 * 2 * (128 + 64) * 64 * 2;   // 98304 (BN=64 variant)
    const int SMLN  = 2 * 2 * (32 + 256) * 64 * 2;   // 147456
    cudaFuncSetAttribute(hgemm3_kernel<64,4,2,0,0,0,1>, cudaFuncAttributeMaxDynamicSharedMemorySize, SM64);
    cudaFuncSetAttribute(hgemm3_kernel<64,4,2,1,0,0,1>, cudaFuncAttributeMaxDynamicSharedMemorySize, SM64);
    cudaFuncSetAttribute(hgemm3_kernel<64,4,2,0,1,1,1>, cudaFuncAttributeMaxDynamicSharedMemorySize, SM64);
    cudaFuncSetAttribute(gemmln_kernel, cudaFuncAttributeMaxDynamicSharedMemorySize, SMLN);

    // merged weight conversion (one launch)
    CvtArgs ca;
    ca.s[0] = Win_a;  ca.h[0] = WinaH;  ca.l[0] = WinaL;
    ca.s[1] = Wout_a; ca.h[1] = WoutaH; ca.l[1] = WoutaL;
    ca.s[2] = Win_e;  ca.h[2] = WineH;  ca.l[2] = WineL;
    ca.s[3] = Wout_e; ca.h[3] = WouteH; ca.l[3] = WouteL;
    ca.s[4] = W1;     ca.h[4] = W1H;    ca.l[4] = W1L;
    ca.s[5] = W2;     ca.h[5] = W2H;    ca.l[5] = W2L;
    int sizes[6] = {2*D3*DD, 2*DD*DD, 2*D3*DD, 2*DD*DD, 2*MLPD*DD, 2*DD*MLPD};
    ca.off[0] = 0;
    for (int i = 0; i < 6; i++) ca.off[i + 1] = ca.off[i] + sizes[i];
    f2h2all_kernel<<<(ca.off[6] + 255) / 256, 256>>>(ca);

    dim3 attn_grid_split(2 * SS / 64, HH, BB);   // 1024 blocks
    dim3 attn_grid(SS / 64, HH, BB);             // banded

    posadd_kernel<<<NROWS, 256>>>(x_in, scale, X, Xh, Xl);

    for (int l = 0; l < 2; l++) {
        const __half* wiaH = WinaH  + l * D3 * DD;   const __half* wiaL = WinaL  + l * D3 * DD;
        const __half* woaH = WoutaH + l * DD * DD;   const __half* woaL = WoutaL + l * DD * DD;
        const __half* wieH = WineH  + l * D3 * DD;   const __half* wieL = WineL  + l * D3 * DD;
        const __half* woeH = WouteH + l * DD * DD;   const __half* woeL = WouteL + l * DD * DD;
        const __half* w1h  = W1H    + l * MLPD * DD; const __half* w1l  = W1L    + l * MLPD * DD;
        const __half* w2h  = W2H    + l * DD * MLPD; const __half* w2l  = W2L    + l * DD * MLPD;
        const float* bia = bin_a + l * D3;
        const float* boa = bout_a + l * DD;
        const float* bie = bin_e + l * D3;
        const float* boe = bout_e + l * DD;

        // full self-attention sublayer: split-K attention + combine
        hgemm3_kernel<64,4,2,0,0,0,1><<<dim3(D3/64, NROWS/128), 256, SM64>>>(
            Xh, Xl, wiaH, wiaL, bia, nullptr, nullptr, QKVh, QKVl, NROWS, D3, DD);
        attn2_kernel<0,1><<<attn_grid_split, 128>>>(QKVh, QKVl, nullptr, nullptr, PO, PM, PL);
        attncomb_kernel<<<NROWS, 256>>>(PO, PM, PL, AOh, AOl);
        gemmln_kernel<<<NROWS/32, 256, SMLN>>>(
            AOh, AOl, woaH, woaL, boa, X, ln1_g + l*DD, ln1_b + l*DD, X, Xh, Xl);

        // banded attention sublayer (3 key-tiles; no split)
        hgemm3_kernel<64,4,2,0,0,0,1><<<dim3(D3/64, NROWS/128), 256, SM64>>>(
            Xh, Xl, wieH, wieL, bie, nullptr, nullptr, QKVh, QKVl, NROWS, D3, DD);
        attn2_kernel<1,0><<<attn_grid, 128>>>(QKVh, QKVl, AOh, AOl, nullptr, nullptr, nullptr);
        gemmln_kernel<<<NROWS/32, 256, SMLN>>>(
            AOh, AOl, woeH, woeL, boe, X, ln2_g + l*DD, ln2_b + l*DD, X, Xh, Xl);

        // MLP (split)
        hgemm3_kernel<64,4,2,1,0,0,1><<<dim3(MLPD/64, NROWS/128), 256, SM64>>>(
            Xh, Xl, w1h, w1l, b1 + l*MLPD, nullptr, nullptr, Hh, Hl, NROWS, MLPD, DD);
        hgemm3_kernel<64,4,2,0,1,1,1><<<dim3(DD/64, NROWS/128), 256, SM64>>>(
            Hh, Hl, w2h, w2l, b2 + l*DD, X, X, Xh, Xl, NROWS, DD, MLPD);
    }

    ln_kernel<<<NROWS, 256>>>(X, lnf_g, lnf_b, out);
}

// round 15
// speedup vs baseline: 1.0254x; 1.0254x over previous
#include <cuda_runtime.h>
#include <cuda_fp16.h>
#include <cstdint>

#define BB 4
#define SS 1024
#define DD 256
#define HH 8
#define HDIM 32
#define D3 768
#define MLPD 1024
#define NROWS (BB*SS)   // 4096

// ---------------- scratch (device globals; no allocation allowed) ----------------
__device__ float g_x  [NROWS * DD];    // fp32 activations (residual stream)
__device__ __align__(16) __half g_xh  [NROWS * DD];    // activations hi
__device__ __align__(16) __half g_xl  [NROWS * DD];    // activations lo
__device__ __align__(16) __half g_qkvh[NROWS * D3];    // qkv hi
__device__ __align__(16) __half g_qkvl[NROWS * D3];    // qkv lo
__device__ __align__(16) __half g_aoh [NROWS * DD];    // attention out hi
__device__ __align__(16) __half g_aol [NROWS * DD];    // attention out lo
__device__ __align__(16) __half g_hh  [NROWS * MLPD];  // MLP hidden hi
__device__ __align__(16) __half g_hl  [NROWS * MLPD];  // MLP hidden lo
// split-K attention partials (2 splits)
__device__ float g_po[2 * NROWS * DD];   // unnormalized partial O
__device__ float g_pm[2 * NROWS * HH];   // row max
__device__ float g_pl[2 * NROWS * HH];   // row sum
// split weights (converted once per call)
__device__ __align__(16) __half g_wina_h [2 * D3 * DD],   g_wina_l [2 * D3 * DD];
__device__ __align__(16) __half g_wouta_h[2 * DD * DD],   g_wouta_l[2 * DD * DD];
__device__ __align__(16) __half g_wine_h [2 * D3 * DD],   g_wine_l [2 * D3 * DD];
__device__ __align__(16) __half g_woute_h[2 * DD * DD],   g_woute_l[2 * DD * DD];
__device__ __align__(16) __half g_w1_h   [2 * MLPD * DD], g_w1_l   [2 * MLPD * DD];
__device__ __align__(16) __half g_w2_h   [2 * DD * MLPD], g_w2_l   [2 * DD * MLPD];

// ---------------- helpers ----------------
__device__ __forceinline__ void cp16(uint32_t dst, const void* src) {
    asm volatile("cp.async.cg.shared.global [%0], [%1], 16;" :: "r"(dst), "l"(src));
}
__device__ __forceinline__ void cp_commit() { asm volatile("cp.async.commit_group;"); }
template <int N> __device__ __forceinline__ void cp_wait() {
    asm volatile("cp.async.wait_group %0;" :: "n"(N));
}
#define LDMX4(r0, r1, r2, r3, addr) \
    asm volatile("ldmatrix.sync.aligned.m8n8.x4.shared.b16 {%0,%1,%2,%3}, [%4];" \
        : "=r"(r0), "=r"(r1), "=r"(r2), "=r"(r3) : "r"(addr))
#define LDMX4T(r0, r1, r2, r3, addr) \
    asm volatile("ldmatrix.sync.aligned.m8n8.x4.trans.shared.b16 {%0,%1,%2,%3}, [%4];" \
        : "=r"(r0), "=r"(r1), "=r"(r2), "=r"(r3) : "r"(addr))
#define MMA16816(d, a, b) \
    asm volatile("mma.sync.aligned.m16n8k16.row.col.f32.f16.f16.f32 " \
        "{%0,%1,%2,%3}, {%4,%5,%6,%7}, {%8,%9}, {%0,%1,%2,%3};" \
        : "+f"(d[0]), "+f"(d[1]), "+f"(d[2]), "+f"(d[3]) \
        : "r"(a[0]), "r"(a[1]), "r"(a[2]), "r"(a[3]), "r"(b[0]), "r"(b[1]))

__device__ __forceinline__ void split2(float v, __half& hi, __half& lo) {
    hi = __float2half(v);
    lo = __float2half(v - __half2float(hi));
}
__device__ __forceinline__ uint32_t packh2(__half a, __half b) {
    __half2 h = __halves2half2(a, b);
    return *(uint32_t*)&h;
}
// swizzled offset (halfs) of the 8-half chunk (row r, chunk ck in 0..3) of a 64x32-half tile
__device__ __forceinline__ int swoff(int r, int ck) {
    return (r >> 1) * 64 + (((((r & 1) << 2) | ck) ^ ((r >> 1) & 7)) << 3);
}

// ---------------- merged fp32 -> (hi, lo) fp16 pair conversion (float4 vectorized) --
struct CvtArgs {
    const float* s[6];
    __half* h[6];
    __half* l[6];
    int off[7];
};
__global__ void f2h2all_kernel(CvtArgs a) {
    int i = (blockIdx.x * blockDim.x + threadIdx.x) * 4;
    if (i >= a.off[6]) return;
    int seg = 0;
#pragma unroll
    for (int s = 1; s < 6; s++) if (i >= a.off[s]) seg = s;
    int j = i - a.off[seg];
    float4 v = *(const float4*)(a.s[seg] + j);
    __half h0, l0, h1, l1, h2, l2, h3, l3;
    split2(v.x, h0, l0); split2(v.y, h1, l1);
    split2(v.z, h2, l2); split2(v.w, h3, l3);
    *(__half2*)(a.h[seg] + j)     = __halves2half2(h0, h1);
    *(__half2*)(a.h[seg] + j + 2) = __halves2half2(h2, h3);
    *(__half2*)(a.l[seg] + j)     = __halves2half2(l0, l1);
    *(__half2*)(a.l[seg] + j + 2) = __halves2half2(l2, l3);
}

// ---------------- pos add ----------------
__global__ void posadd_kernel(const float* __restrict__ xin, const float* __restrict__ scale,
                              float* __restrict__ out, __half* __restrict__ oh,
                              __half* __restrict__ ol) {
    int row = blockIdx.x;
    int d = threadIdx.x;
    int s = row & (SS - 1);
    float v = xin[row * DD + d] + (float)s * scale[0];
    out[row * DD + d] = v;
    __half h, l; split2(v, h, l);
    oh[row * DD + d] = h; ol[row * DD + d] = l;
}

// ---------------- final layernorm (warp-shuffle reduction, 2 barriers) ----------------
__global__ void ln_kernel(const float* __restrict__ in, const float* __restrict__ gam,
                          const float* __restrict__ bet, float* __restrict__ out) {
    int row = blockIdx.x;
    int tid = threadIdx.x;
    __shared__ float ws[8], wq[8];
    float v = in[row * DD + tid];
    float s = v, q = v * v;
#pragma unroll
    for (int o = 16; o > 0; o >>= 1) {
        s += __shfl_xor_sync(0xffffffffu, s, o);
        q += __shfl_xor_sync(0xffffffffu, q, o);
    }
    if ((tid & 31) == 0) { ws[tid >> 5] = s; wq[tid >> 5] = q; }
    __syncthreads();
    float sum = 0.0f, sq = 0.0f;
#pragma unroll
    for (int i = 0; i < 8; i++) { sum += ws[i]; sq += wq[i]; }
    float mean = sum * (1.0f / DD);
    float var = sq * (1.0f / DD) - mean * mean;
    out[row * DD + tid] = (v - mean) * rsqrtf(var + 1e-5f) * gam[tid] + bet[tid];
}

// ---------------- split-fp16 tensor-core GEMM: C = act(A @ B^T + bias) (+res) ------
// BM=128, BK=64, 2-stage, 3-term split.
template <int BN, int WM_, int WN_, int ACT, int RES, int OUTF, int OUTH>
__global__ void __launch_bounds__(256)
hgemm3_kernel(const __half* __restrict__ Ah, const __half* __restrict__ Al,
              const __half* __restrict__ Bh, const __half* __restrict__ Bl,
              const float* __restrict__ bias, const float* __restrict__ res,
              float* __restrict__ C, __half* __restrict__ Chh, __half* __restrict__ Chl,
              int M, int N, int K) {
    constexpr int BM = 128, BK = 64;
    constexpr int MITER = BM / (WM_ * 16);
    constexpr int NITER = BN / (WN_ * 8);
    constexpr int ASZ = BM * BK, BSZ = BN * BK;
    constexpr int SSZ = 2 * ASZ + 2 * BSZ;   // halfs per stage: Ah|Al|Bh|Bl

    extern __shared__ __half smh[];
    const int tid = threadIdx.x;
    const int lane = tid & 31, warp = tid >> 5;
    const int wm = warp / WN_, wn = warp % WN_;
    const int m0 = blockIdx.y * BM, n0 = blockIdx.x * BN;
    const uint32_t sbase = (uint32_t)__cvta_generic_to_shared(smh);
    const int nt = K / BK;

    auto load_tile = [&](int stg, int kt) {
        uint32_t s0 = sbase + (uint32_t)(stg * SSZ) * 2u;
#pragma unroll
        for (int i = 0; i < BM * 8 / 256; i++) {
            int c = tid + i * 256;
            int r = c >> 3, ck = c & 7;
            uint32_t off = (uint32_t)(r * BK + ((ck ^ (r & 7)) << 3)) * 2u;
            const size_t gi = (size_t)(m0 + r) * K + kt * BK + ck * 8;
            cp16(s0 + off, Ah + gi);
            cp16(s0 + (uint32_t)ASZ * 2u + off, Al + gi);
        }
#pragma unroll
        for (int i = 0; i < BN * 8 / 256; i++) {
            int c = tid + i * 256;
            int r = c >> 3, ck = c & 7;
            uint32_t off = (uint32_t)(r * BK + ((ck ^ (r & 7)) << 3)) * 2u;
            const size_t gi = (size_t)(n0 + r) * K + kt * BK + ck * 8;
            cp16(s0 + (uint32_t)(2 * ASZ) * 2u + off, Bh + gi);
            cp16(s0 + (uint32_t)(2 * ASZ + BSZ) * 2u + off, Bl + gi);
        }
    };

    float acc[MITER][NITER][4];
#pragma unroll
    for (int i = 0; i < MITER; i++)
#pragma unroll
        for (int j = 0; j < NITER; j++)
#pragma unroll
            for (int q = 0; q < 4; q++) acc[i][j][q] = 0.0f;

    load_tile(0, 0);
    cp_commit();

    for (int t = 0; t < nt; t++) {
        cp_wait<0>();
        __syncthreads();
        if (t + 1 < nt) load_tile((t + 1) & 1, t + 1);
        cp_commit();

        int stg = t & 1;
        uint32_t ahb = sbase + (uint32_t)(stg * SSZ) * 2u;
        uint32_t alb = ahb + (uint32_t)ASZ * 2u;
        uint32_t bhb = ahb + (uint32_t)(2 * ASZ) * 2u;
        uint32_t blb = ahb + (uint32_t)(2 * ASZ + BSZ) * 2u;
#pragma unroll
        for (int ks = 0; ks < BK / 16; ks++) {
            uint32_t ah[MITER][4], al[MITER][4];
            uint32_t bh[NITER][2], bl[NITER][2];
#pragma unroll
            for (int i = 0; i < MITER; i++) {
                int r = wm * MITER * 16 + i * 16 + (lane & 15);
                int ck = ks * 2 + (lane >> 4);
                uint32_t off = (uint32_t)(r * BK + ((ck ^ (r & 7)) << 3)) * 2u;
                LDMX4(ah[i][0], ah[i][1], ah[i][2], ah[i][3], ahb + off);
                LDMX4(al[i][0], al[i][1], al[i][2], al[i][3], alb + off);
            }
#pragma unroll
            for (int j = 0; j < NITER / 2; j++) {
                int r = wn * NITER * 8 + j * 16 + (lane & 7) + ((lane >> 4) << 3);
                int ck = ks * 2 + ((lane >> 3) & 1);
                uint32_t off = (uint32_t)(r * BK + ((ck ^ (r & 7)) << 3)) * 2u;
                LDMX4(bh[2 * j][0], bh[2 * j][1], bh[2 * j + 1][0], bh[2 * j + 1][1], bhb + off);
                LDMX4(bl[2 * j][0], bl[2 * j][1], bl[2 * j + 1][0], bl[2 * j + 1][1], blb + off);
            }
#pragma unroll
            for (int i = 0; i < MITER; i++)
#pragma unroll
                for (int j = 0; j < NITER; j++) {
                    MMA16816(acc[i][j], ah[i], bh[j]);
                    MMA16816(acc[i][j], al[i], bh[j]);
                    MMA16816(acc[i][j], ah[i], bl[j]);
                }
        }
        __syncthreads();
    }

    // epilogue
#pragma unroll
    for (int i = 0; i < MITER; i++) {
#pragma unroll
        for (int j = 0; j < NITER; j++) {
            int m = m0 + wm * MITER * 16 + i * 16 + (lane >> 2);
            int n = n0 + wn * NITER * 8 + j * 8 + (lane & 3) * 2;
            float2 bb = *(const float2*)(bias + n);
            float v0 = acc[i][j][0] + bb.x;
            float v1 = acc[i][j][1] + bb.y;
            float v2 = acc[i][j][2] + bb.x;
            float v3 = acc[i][j][3] + bb.y;
            if (ACT) {
                v0 = 0.5f * v0 * (1.0f + erff(v0 * 0.70710678118654752f));
                v1 = 0.5f * v1 * (1.0f + erff(v1 * 0.70710678118654752f));
                v2 = 0.5f * v2 * (1.0f + erff(v2 * 0.70710678118654752f));
                v3 = 0.5f * v3 * (1.0f + erff(v3 * 0.70710678118654752f));
            }
            if (RES) {
                float2 r0 = *(const float2*)(res + (size_t)m * N + n);
                float2 r1 = *(const float2*)(res + (size_t)(m + 8) * N + n);
                v0 += r0.x; v1 += r0.y; v2 += r1.x; v3 += r1.y;
            }
            if (OUTF) {
                *(float2*)(C + (size_t)m * N + n) = make_float2(v0, v1);
                *(float2*)(C + (size_t)(m + 8) * N + n) = make_float2(v2, v3);
            }
            if (OUTH) {
                __half h0, l0, h1, l1, h2, l2, h3, l3;
                split2(v0, h0, l0); split2(v1, h1, l1);
                split2(v2, h2, l2); split2(v3, h3, l3);
                *(__half2*)(Chh + (size_t)m * N + n)       = __halves2half2(h0, h1);
                *(__half2*)(Chh + (size_t)(m + 8) * N + n) = __halves2half2(h2, h3);
                *(__half2*)(Chl + (size_t)m * N + n)       = __halves2half2(l0, l1);
                *(__half2*)(Chl + (size_t)(m + 8) * N + n) = __halves2half2(l2, l3);
            }
        }
    }
}

// ---------------- fused out-proj GEMM + residual + LayerNorm (split fp16) ----------
__global__ void __launch_bounds__(256)
gemmln_kernel(const __half* __restrict__ Ah, const __half* __restrict__ Al,
              const __half* __restrict__ Bh, const __half* __restrict__ Bl,
              const float* __restrict__ bias, const float* __restrict__ res,
              const float* __restrict__ gam, const float* __restrict__ bet,
              float* __restrict__ X, __half* __restrict__ Xh, __half* __restrict__ Xl) {
    constexpr int BM = 32, BN = 256, BK = 64, K = 256, N = 256;
    constexpr int NITER = 8;
    constexpr int ASZ = BM * BK, BSZ = BN * BK;
    constexpr int SSZ = 2 * ASZ + 2 * BSZ;
    constexpr int nt = K / BK;

    extern __shared__ __half smh[];
    __shared__ float ps[32][4], pq[32][4];
    const int tid = threadIdx.x;
    const int lane = tid & 31, warp = tid >> 5;
    const int wm = warp >> 2, wn = warp & 3;
    const int g = lane >> 2, t = lane & 3;
    const int m0 = blockIdx.x * BM;
    const uint32_t sbase = (uint32_t)__cvta_generic_to_shared(smh);

    auto load_tile = [&](int stg, int kt) {
        uint32_t s0 = sbase + (uint32_t)(stg * SSZ) * 2u;
        {
            int r = tid >> 3, ck = tid & 7;
            uint32_t off = (uint32_t)(r * BK + ((ck ^ (r & 7)) << 3)) * 2u;
            const size_t gi = (size_t)(m0 + r) * K + kt * BK + ck * 8;
            cp16(s0 + off, Ah + gi);
            cp16(s0 + (uint32_t)ASZ * 2u + off, Al + gi);
        }
#pragma unroll
        for (int i = 0; i < 8; i++) {
            int c = tid + i * 256;
            int r = c >> 3, ck = c & 7;
            uint32_t off = (uint32_t)(r * BK + ((ck ^ (r & 7)) << 3)) * 2u;
            const size_t gi = (size_t)r * K + kt * BK + ck * 8;
            cp16(s0 + (uint32_t)(2 * ASZ) * 2u + off, Bh + gi);
            cp16(s0 + (uint32_t)(2 * ASZ + BSZ) * 2u + off, Bl + gi);
        }
    };

    float acc[NITER][4];
#pragma unroll
    for (int j = 0; j < NITER; j++)
#pragma unroll
        for (int q = 0; q < 4; q++) acc[j][q] = 0.0f;

    load_tile(0, 0);
    cp_commit();

    for (int tt = 0; tt < nt; tt++) {
        cp_wait<0>();
        __syncthreads();
        if (tt + 1 < nt) load_tile((tt + 1) & 1, tt + 1);
        cp_commit();

        int stg = tt & 1;
        uint32_t ahb = sbase + (uint32_t)(stg * SSZ) * 2u;
        uint32_t alb = ahb + (uint32_t)ASZ * 2u;
        uint32_t bhb = ahb + (uint32_t)(2 * ASZ) * 2u;
        uint32_t blb = ahb + (uint32_t)(2 * ASZ + BSZ) * 2u;
#pragma unroll
        for (int ks = 0; ks < BK / 16; ks++) {
            uint32_t ah[4], al[4];
            {
                int r = wm * 16 + (lane & 15);
                int ck = ks * 2 + (lane >> 4);
                uint32_t off = (uint32_t)(r * BK + ((ck ^ (r & 7)) << 3)) * 2u;
                LDMX4(ah[0], ah[1], ah[2], ah[3], ahb + off);
                LDMX4(al[0], al[1], al[2], al[3], alb + off);
            }
            uint32_t bh[NITER][2], bl[NITER][2];
#pragma unroll
            for (int j = 0; j < NITER / 2; j++) {
                int r = wn * 64 + j * 16 + (lane & 7) + ((lane >> 4) << 3);
                int ck = ks * 2 + ((lane >> 3) & 1);
                uint32_t off = (uint32_t)(r * BK + ((ck ^ (r & 7)) << 3)) * 2u;
                LDMX4(bh[2 * j][0], bh[2 * j][1], bh[2 * j + 1][0], bh[2 * j + 1][1], bhb + off);
                LDMX4(bl[2 * j][0], bl[2 * j][1], bl[2 * j + 1][0], bl[2 * j + 1][1], blb + off);
            }
#pragma unroll
            for (int j = 0; j < NITER; j++) {
                MMA16816(acc[j], ah, bh[j]);
                MMA16816(acc[j], al, bh[j]);
                MMA16816(acc[j], ah, bl[j]);
            }
        }
        __syncthreads();
    }

    const int lrA = wm * 16 + g;
    const int lrB = lrA + 8;
    const int mA = m0 + lrA, mB = m0 + lrB;

    float sA = 0.0f, qA = 0.0f, sB = 0.0f, qB = 0.0f;
#pragma unroll
    for (int j = 0; j < NITER; j++) {
        int n = wn * 64 + j * 8 + t * 2;
        float2 bb = *(const float2*)(bias + n);
        float2 r0 = *(const float2*)(res + (size_t)mA * N + n);
        float2 r1 = *(const float2*)(res + (size_t)mB * N + n);
        float v0 = acc[j][0] + bb.x + r0.x;
        float v1 = acc[j][1] + bb.y + r0.y;
        float v2 = acc[j][2] + bb.x + r1.x;
        float v3 = acc[j][3] + bb.y + r1.y;
        acc[j][0] = v0; acc[j][1] = v1; acc[j][2] = v2; acc[j][3] = v3;
        sA += v0 + v1; qA += v0 * v0 + v1 * v1;
        sB += v2 + v3; qB += v2 * v2 + v3 * v3;
    }
    sA += __shfl_xor_sync(0xffffffffu, sA, 1); sA += __shfl_xor_sync(0xffffffffu, sA, 2);
    qA += __shfl_xor_sync(0xffffffffu, qA, 1); qA += __shfl_xor_sync(0xffffffffu, qA, 2);
    sB += __shfl_xor_sync(0xffffffffu, sB, 1); sB += __shfl_xor_sync(0xffffffffu, sB, 2);
    qB += __shfl_xor_sync(0xffffffffu, qB, 1); qB += __shfl_xor_sync(0xffffffffu, qB, 2);
    if (t == 0) { ps[lrA][wn] = sA; pq[lrA][wn] = qA; ps[lrB][wn] = sB; pq[lrB][wn] = qB; }
    __syncthreads();

    float sumA = ps[lrA][0] + ps[lrA][1] + ps[lrA][2] + ps[lrA][3];
    float sqA  = pq[lrA][0] + pq[lrA][1] + pq[lrA][2] + pq[lrA][3];
    float sumB = ps[lrB][0] + ps[lrB][1] + ps[lrB][2] + ps[lrB][3];
    float sqB  = pq[lrB][0] + pq[lrB][1] + pq[lrB][2] + pq[lrB][3];
    float meanA = sumA * (1.0f / N), meanB = sumB * (1.0f / N);
    float varA = sqA * (1.0f / N) - meanA * meanA;
    float varB = sqB * (1.0f / N) - meanB * meanB;
    float rA = rsqrtf(varA + 1e-5f), rB = rsqrtf(varB + 1e-5f);

#pragma unroll
    for (int j = 0; j < NITER; j++) {
        int n = wn * 64 + j * 8 + t * 2;
        float2 gg = *(const float2*)(gam + n);
        float2 be = *(const float2*)(bet + n);
        float y0 = (acc[j][0] - meanA) * rA * gg.x + be.x;
        float y1 = (acc[j][1] - meanA) * rA * gg.y + be.y;
        float y2 = (acc[j][2] - meanB) * rB * gg.x + be.x;
        float y3 = (acc[j][3] - meanB) * rB * gg.y + be.y;
        *(float2*)(X + (size_t)mA * N + n) = make_float2(y0, y1);
        *(float2*)(X + (size_t)mB * N + n) = make_float2(y2, y3);
        __half h0, l0, h1, l1, h2, l2, h3, l3;
        split2(y0, h0, l0); split2(y1, h1, l1);
        split2(y2, h2, l2); split2(y3, h3, l3);
        *(__half2*)(Xh + (size_t)mA * N + n) = __halves2half2(h0, h1);
        *(__half2*)(Xl + (size_t)mA * N + n) = __halves2half2(l0, l1);
        *(__half2*)(Xh + (size_t)mB * N + n) = __halves2half2(h2, h3);
        *(__half2*)(Xl + (size_t)mB * N + n) = __halves2half2(l2, l3);
    }
}

// ---------------- tensor-core flash attention (split fp16, fp32 softmax) ----------------
// 128 threads, 64 q-rows per block (round-13 proven version).
template <int BANDED, int SPLITK>
__global__ void __launch_bounds__(128)
attn2_kernel(const __half* __restrict__ qh, const __half* __restrict__ ql,
             __half* __restrict__ aoh, __half* __restrict__ aol,
             float* __restrict__ po, float* __restrict__ pm, float* __restrict__ pl) {
    __shared__ __half sm[20480];
    int qt, sp = 0;
    if (SPLITK) { qt = blockIdx.x >> 1; sp = blockIdx.x & 1; }
    else        { qt = blockIdx.x; }
    const int h = blockIdx.y, b = blockIdx.z;
    const int q0 = qt * 64;
    const int tid = threadIdx.x;
    const int lane = tid & 31, w = tid >> 5;
    const int g = lane >> 2, t = lane & 3;
    const uint32_t sb = (uint32_t)__cvta_generic_to_shared(sm);

#pragma unroll
    for (int i = 0; i < 4; i++) {
        int idx = tid + i * 128;
        int matl = idx >> 8;
        int c = idx & 255;
        int r = c >> 2, ck = c & 3;
        const __half* src = (matl ? ql : qh) + (size_t)(b * SS + q0 + r) * D3 + h * HDIM + ck * 8;
        cp16(sb + (uint32_t)(matl * 2048 + swoff(r, ck)) * 2u, src);
    }

    int jt0, jt1;
    if (SPLITK)      { jt0 = sp * 8; jt1 = jt0 + 7; }
    else if (BANDED) { jt0 = max(0, qt - 1); jt1 = min(SS / 64 - 1, qt + 1); }
    else             { jt0 = 0; jt1 = SS / 64 - 1; }

    auto stage_kv = [&](int buf, int jt) {
        int j0 = jt * 64;
#pragma unroll
        for (int i = 0; i < 8; i++) {
            int idx = tid + i * 128;
            int mat = idx >> 8;
            int c = idx & 255;
            int r = c >> 2, ck = c & 3;
            int sec = (mat >> 1) ? 2 * DD : DD;
            const __half* src = ((mat & 1) ? ql : qh)
                + (size_t)(b * SS + j0 + r) * D3 + sec + h * HDIM + ck * 8;
            cp16(sb + (uint32_t)(4096 + buf * 8192 + mat * 2048 + swoff(r, ck)) * 2u, src);
        }
    };

    stage_kv(0, jt0);
    cp_commit();
    cp_wait<0>();
    __syncthreads();

    uint32_t ah[2][4], al[2][4];
    {
        int r = w * 16 + (lane & 15);
#pragma unroll
        for (int kb = 0; kb < 2; kb++) {
            int ck = kb * 2 + (lane >> 4);
            uint32_t off = (uint32_t)swoff(r, ck) * 2u;
            LDMX4(ah[kb][0], ah[kb][1], ah[kb][2], ah[kb][3], sb + off);
            LDMX4(al[kb][0], al[kb][1], al[kb][2], al[kb][3], sb + 4096u + off);
        }
    }

    float o[4][4];
#pragma unroll
    for (int dn = 0; dn < 4; dn++)
#pragma unroll
        for (int q = 0; q < 4; q++) o[dn][q] = 0.0f;
    float mA = -1e30f, mB = -1e30f, lA = 0.0f, lB = 0.0f;
    const float scl = 0.17677669529663687f;

    for (int jt = jt0; jt <= jt1; jt++) {
        int buf = (jt - jt0) & 1;
        if (jt < jt1) { stage_kv(buf ^ 1, jt + 1); cp_commit(); }
        uint32_t kvb = sb + (uint32_t)(4096 + buf * 8192) * 2u;

        float accs[8][4];
#pragma unroll
        for (int j = 0; j < 8; j++)
#pragma unroll
            for (int q = 0; q < 4; q++) accs[j][q] = 0.0f;
#pragma unroll
        for (int kb = 0; kb < 2; kb++) {
#pragma unroll
            for (int jg = 0; jg < 4; jg++) {
                int r = jg * 16 + (lane & 7) + ((lane >> 4) << 3);
                int ck = kb * 2 + ((lane >> 3) & 1);
                uint32_t off = (uint32_t)swoff(r, ck) * 2u;
                uint32_t kh[4], kl[4];
                LDMX4(kh[0], kh[1], kh[2], kh[3], kvb + off);
                LDMX4(kl[0], kl[1], kl[2], kl[3], kvb + 4096u + off);
                uint32_t b0h[2] = {kh[0], kh[1]}, b1h[2] = {kh[2], kh[3]};
                uint32_t b0l[2] = {kl[0], kl[1]}, b1l[2] = {kl[2], kl[3]};
                MMA16816(accs[2 * jg],     ah[kb], b0h);
                MMA16816(accs[2 * jg],     al[kb], b0h);
                MMA16816(accs[2 * jg],     ah[kb], b0l);
                MMA16816(accs[2 * jg + 1], ah[kb], b1h);
                MMA16816(accs[2 * jg + 1], al[kb], b1h);
                MMA16816(accs[2 * jg + 1], ah[kb], b1l);
            }
        }

        int j0k = jt * 64;
#pragma unroll
        for (int j = 0; j < 8; j++)
#pragma unroll
            for (int q = 0; q < 4; q++) {
                float s = accs[j][q] * scl;
                if (BANDED) {
                    int qrow = q0 + w * 16 + g + ((q >> 1) << 3);
                    int kcol = j0k + j * 8 + 2 * t + (q & 1);
                    if (abs(qrow - kcol) > 64) s = -1.0e9f;
                }
                accs[j][q] = s;
            }

        float cmA = -1e30f, cmB = -1e30f;
#pragma unroll
        for (int j = 0; j < 8; j++) {
            cmA = fmaxf(cmA, fmaxf(accs[j][0], accs[j][1]));
            cmB = fmaxf(cmB, fmaxf(accs[j][2], accs[j][3]));
        }
        cmA = fmaxf(cmA, __shfl_xor_sync(0xffffffffu, cmA, 1));
        cmA = fmaxf(cmA, __shfl_xor_sync(0xffffffffu, cmA, 2));
        cmB = fmaxf(cmB, __shfl_xor_sync(0xffffffffu, cmB, 1));
        cmB = fmaxf(cmB, __shfl_xor_sync(0xffffffffu, cmB, 2));
        float nmA = fmaxf(mA, cmA), nmB = fmaxf(mB, cmB);
        float aA = __expf(mA - nmA), aB = __expf(mB - nmB);
        mA = nmA; mB = nmB;

        float tsA = 0.0f, tsB = 0.0f;
        uint32_t pah[4][4], pal[4][4];
#pragma unroll
        for (int kk = 0; kk < 4; kk++) {
#pragma unroll
            for (int jj = 0; jj < 2; jj++) {
                int j = 2 * kk + jj;
                float p0 = __expf(accs[j][0] - nmA);
                float p1 = __expf(accs[j][1] - nmA);
                float p2 = __expf(accs[j][2] - nmB);
                float p3 = __expf(accs[j][3] - nmB);
                tsA += p0 + p1; tsB += p2 + p3;
                __half h0, l0, h1, l1, h2, l2, h3, l3;
                split2(p0, h0, l0); split2(p1, h1, l1);
                split2(p2, h2, l2); split2(p3, h3, l3);
                pah[kk][0 + 2 * jj] = packh2(h0, h1);
                pah[kk][1 + 2 * jj] = packh2(h2, h3);
                pal[kk][0 + 2 * jj] = packh2(l0, l1);
                pal[kk][1 + 2 * jj] = packh2(l2, l3);
            }
        }
        tsA += __shfl_xor_sync(0xffffffffu, tsA, 1);
        tsA += __shfl_xor_sync(0xffffffffu, tsA, 2);
        tsB += __shfl_xor_sync(0xffffffffu, tsB, 1);
        tsB += __shfl_xor_sync(0xffffffffu, tsB, 2);
        lA = lA * aA + tsA;
        lB = lB * aB + tsB;
#pragma unroll
        for (int dn = 0; dn < 4; dn++) {
            o[dn][0] *= aA; o[dn][1] *= aA; o[dn][2] *= aB; o[dn][3] *= aB;
        }

#pragma unroll
        for (int dnp = 0; dnp < 2; dnp++) {
#pragma unroll
            for (int kk = 0; kk < 4; kk++) {
                int r = kk * 16 + ((lane >> 3) & 1) * 8 + (lane & 7);
                int ck = dnp * 2 + (lane >> 4);
                uint32_t off = (uint32_t)swoff(r, ck) * 2u;
                uint32_t vh[4], vl[4];
                LDMX4T(vh[0], vh[1], vh[2], vh[3], kvb + 8192u + off);
                LDMX4T(vl[0], vl[1], vl[2], vl[3], kvb + 12288u + off);
                uint32_t b0h[2] = {vh[0], vh[1]}, b1h[2] = {vh[2], vh[3]};
                uint32_t b0l[2] = {vl[0], vl[1]}, b1l[2] = {vl[2], vl[3]};
                MMA16816(o[2 * dnp],     pah[kk], b0h);
                MMA16816(o[2 * dnp],     pal[kk], b0h);
                MMA16816(o[2 * dnp],     pah[kk], b0l);
                MMA16816(o[2 * dnp + 1], pah[kk], b1h);
                MMA16816(o[2 * dnp + 1], pal[kk], b1h);
                MMA16816(o[2 * dnp + 1], pah[kk], b1l);
            }
        }

        if (jt < jt1) cp_wait<0>();
        __syncthreads();
    }

    int rowA = b * SS + q0 + w * 16 + g;
    if (SPLITK) {
        float* poS = po + (size_t)sp * NROWS * DD;
#pragma unroll
        for (int dn = 0; dn < 4; dn++) {
            int col = h * HDIM + dn * 8 + 2 * t;
            *(float2*)(poS + (size_t)rowA * DD + col)       = make_float2(o[dn][0], o[dn][1]);
            *(float2*)(poS + (size_t)(rowA + 8) * DD + col) = make_float2(o[dn][2], o[dn][3]);
        }
        if (t == 0) {
            pm[(size_t)sp * NROWS * HH + rowA * HH + h] = mA;
            pl[(size_t)sp * NROWS * HH + rowA * HH + h] = lA;
            pm[(size_t)sp * NROWS * HH + (rowA + 8) * HH + h] = mB;
            pl[(size_t)sp * NROWS * HH + (rowA + 8) * HH + h] = lB;
        }
    } else {
        float invA = 1.0f / lA, invB = 1.0f / lB;
#pragma unroll
        for (int dn = 0; dn < 4; dn++) {
            int col = h * HDIM + dn * 8 + 2 * t;
            float v0 = o[dn][0] * invA, v1 = o[dn][1] * invA;
            float v2 = o[dn][2] * invB, v3 = o[dn][3] * invB;
            __half h0, l0, h1, l1, h2, l2, h3, l3;
            split2(v0, h0, l0); split2(v1, h1, l1);
            split2(v2, h2, l2); split2(v3, h3, l3);
            *(__half2*)(aoh + (size_t)rowA * DD + col)       = __halves2half2(h0, h1);
            *(__half2*)(aol + (size_t)rowA * DD + col)       = __halves2half2(l0, l1);
            *(__half2*)(aoh + (size_t)(rowA + 8) * DD + col) = __halves2half2(h2, h3);
            *(__half2*)(aol + (size_t)(rowA + 8) * DD + col) = __halves2half2(l2, l3);
        }
    }
}

// ---------------- split-K combine: merge 2 partials with log-sum-exp reweighting ----
__global__ void attncomb_kernel(const float* __restrict__ po, const float* __restrict__ pm,
                                const float* __restrict__ pl,
                                __half* __restrict__ aoh, __half* __restrict__ aol) {
    int row = blockIdx.x;
    int c = threadIdx.x;          // 0..255
    int h = c >> 5;
    float m1 = pm[(size_t)row * HH + h];
    float m2 = pm[(size_t)NROWS * HH + row * HH + h];
    float l1 = pl[(size_t)row * HH + h];
    float l2 = pl[(size_t)NROWS * HH + row * HH + h];
    float mm = fmaxf(m1, m2);
    float w1 = __expf(m1 - mm), w2 = __expf(m2 - mm);
    float o1 = po[(size_t)row * DD + c];
    float o2 = po[(size_t)NROWS * DD + row * DD + c];
    float v = (w1 * o1 + w2 * o2) / (w1 * l1 + w2 * l2);
    __half hi, lo; split2(v, hi, lo);
    aoh[(size_t)row * DD + c] = hi;
    aol[(size_t)row * DD + c] = lo;
}

// ---------------- host launch sequence ----------------
extern "C" void kernel_launch(void* const* d_in, const int* in_sizes, int n_in,
                              void* d_out, int out_size) {
    const float* x_in  = (const float*)d_in[0];
    const float* scale = (const float*)d_in[1];
    const float* Win_a = (const float*)d_in[2];
    const float* bin_a = (const float*)d_in[3];
    const float* Wout_a= (const float*)d_in[4];
    const float* bout_a= (const float*)d_in[5];
    const float* Win_e = (const float*)d_in[6];
    const float* bin_e = (const float*)d_in[7];
    const float* Wout_e= (const float*)d_in[8];
    const float* bout_e= (const float*)d_in[9];
    const float* ln1_g = (const float*)d_in[10];
    const float* ln1_b = (const float*)d_in[11];
    const float* ln2_g = (const float*)d_in[12];
    const float* ln2_b = (const float*)d_in[13];
    const float* W1    = (const float*)d_in[14];
    const float* b1    = (const float*)d_in[15];
    const float* W2    = (const float*)d_in[16];
    const float* b2    = (const float*)d_in[17];
    const float* lnf_g = (const float*)d_in[18];
    const float* lnf_b = (const float*)d_in[19];
    float* out = (float*)d_out;

    float *X, *PO, *PM, *PL;
    __half *Xh, *Xl, *QKVh, *QKVl, *AOh, *AOl, *Hh, *Hl;
    __half *WinaH, *WinaL, *WoutaH, *WoutaL, *WineH, *WineL, *WouteH, *WouteL;
    __half *W1H, *W1L, *W2H, *W2L;
    cudaGetSymbolAddress((void**)&X,   g_x);
    cudaGetSymbolAddress((void**)&PO,  g_po);
    cudaGetSymbolAddress((void**)&PM,  g_pm);
    cudaGetSymbolAddress((void**)&PL,  g_pl);
    cudaGetSymbolAddress((void**)&Xh,  g_xh);    cudaGetSymbolAddress((void**)&Xl,  g_xl);
    cudaGetSymbolAddress((void**)&QKVh, g_qkvh); cudaGetSymbolAddress((void**)&QKVl, g_qkvl);
    cudaGetSymbolAddress((void**)&AOh, g_aoh);   cudaGetSymbolAddress((void**)&AOl, g_aol);
    cudaGetSymbolAddress((void**)&Hh,  g_hh);    cudaGetSymbolAddress((void**)&Hl,  g_hl);
    cudaGetSymbolAddress((void**)&WinaH,  g_wina_h);  cudaGetSymbolAddress((void**)&WinaL,  g_wina_l);
    cudaGetSymbolAddress((void**)&WoutaH, g_wouta_h); cudaGetSymbolAddress((void**)&WoutaL, g_wouta_l);
    cudaGetSymbolAddress((void**)&WineH,  g_wine_h);  cudaGetSymbolAddress((void**)&WineL,  g_wine_l);
    cudaGetSymbolAddress((void**)&WouteH, g_woute_h); cudaGetSymbolAddress((void**)&WouteL, g_woute_l);
    cudaGetSymbolAddress((void**)&W1H,    g_w1_h);    cudaGetSymbolAddress((void**)&W1L,    g_w1_l);
    cudaGetSymbolAddress((void**)&W2H,    g_w2_h);    cudaGetSymbolAddress((void**)&W2L,    g_w2_l);

    const int SM64  = 2 * 2 * (128 + 64) * 64 * 2;   // 98304 (BN=64 variant)
    const int SMLN  = 2 * 2 * (32 + 256) * 64 * 2;   // 147456
    cudaFuncSetAttribute(hgemm3_kernel<64,4,2,0,0,0,1>, cudaFuncAttributeMaxDynamicSharedMemorySize, SM64);
    cudaFuncSetAttribute(hgemm3_kernel<64,4,2,1,0,0,1>, cudaFuncAttributeMaxDynamicSharedMemorySize, SM64);
    cudaFuncSetAttribute(hgemm3_kernel<64,4,2,0,1,1,1>, cudaFuncAttributeMaxDynamicSharedMemorySize, SM64);
    cudaFuncSetAttribute(gemmln_kernel, cudaFuncAttributeMaxDynamicSharedMemorySize, SMLN);

    // merged weight conversion (one launch, float4 vectorized)
    CvtArgs ca;
    ca.s[0] = Win_a;  ca.h[0] = WinaH;  ca.l[0] = WinaL;
    ca.s[1] = Wout_a; ca.h[1] = WoutaH; ca.l[1] = WoutaL;
    ca.s[2] = Win_e;  ca.h[2] = WineH;  ca.l[2] = WineL;
    ca.s[3] = Wout_e; ca.h[3] = WouteH; ca.l[3] = WouteL;
    ca.s[4] = W1;     ca.h[4] = W1H;    ca.l[4] = W1L;
    ca.s[5] = W2;     ca.h[5] = W2H;    ca.l[5] = W2L;
    int sizes[6] = {2*D3*DD, 2*DD*DD, 2*D3*DD, 2*DD*DD, 2*MLPD*DD, 2*DD*MLPD};
    ca.off[0] = 0;
    for (int i = 0; i < 6; i++) ca.off[i + 1] = ca.off[i] + sizes[i];
    f2h2all_kernel<<<(ca.off[6] / 4 + 255) / 256, 256>>>(ca);

    dim3 attn_grid_split(2 * SS / 64, HH, BB);   // 1024 blocks
    dim3 attn_grid(SS / 64, HH, BB);             // banded

    posadd_kernel<<<NROWS, 256>>>(x_in, scale, X, Xh, Xl);

    for (int l = 0; l < 2; l++) {
        const __half* wiaH = WinaH  + l * D3 * DD;   const __half* wiaL = WinaL  + l * D3 * DD;
        const __half* woaH = WoutaH + l * DD * DD;   const __half* woaL = WoutaL + l * DD * DD;
        const __half* wieH = WineH  + l * D3 * DD;   const __half* wieL = WineL  + l * D3 * DD;
        const __half* woeH = WouteH + l * DD * DD;   const __half* woeL = WouteL + l * DD * DD;
        const __half* w1h  = W1H    + l * MLPD * DD; const __half* w1l  = W1L    + l * MLPD * DD;
        const __half* w2h  = W2H    + l * DD * MLPD; const __half* w2l  = W2L    + l * DD * MLPD;
        const float* bia = bin_a + l * D3;
        const float* boa = bout_a + l * DD;
        const float* bie = bin_e + l * D3;
        const float* boe = bout_e + l * DD;

        // full self-attention sublayer: split-K attention + combine
        hgemm3_kernel<64,4,2,0,0,0,1><<<dim3(D3/64, NROWS/128), 256, SM64>>>(
            Xh, Xl, wiaH, wiaL, bia, nullptr, nullptr, QKVh, QKVl, NROWS, D3, DD);
        attn2_kernel<0,1><<<attn_grid_split, 128>>>(QKVh, QKVl, nullptr, nullptr, PO, PM, PL);
        attncomb_kernel<<<NROWS, 256>>>(PO, PM, PL, AOh, AOl);
        gemmln_kernel<<<NROWS/32, 256, SMLN>>>(
            AOh, AOl, woaH, woaL, boa, X, ln1_g + l*DD, ln1_b + l*DD, X, Xh, Xl);

        // banded attention sublayer (3 key-tiles; no split)
        hgemm3_kernel<64,4,2,0,0,0,1><<<dim3(D3/64, NROWS/128), 256, SM64>>>(
            Xh, Xl, wieH, wieL, bie, nullptr, nullptr, QKVh, QKVl, NROWS, D3, DD);
        attn2_kernel<1,0><<<attn_grid, 128>>>(QKVh, QKVl, AOh, AOl, nullptr, nullptr, nullptr);
        gemmln_kernel<<<NROWS/32, 256, SMLN>>>(
            AOh, AOl, woeH, woeL, boe, X, ln2_g + l*DD, ln2_b + l*DD, X, Xh, Xl);

        // MLP (split)
        hgemm3_kernel<64,4,2,1,0,0,1><<<dim3(MLPD/64, NROWS/128), 256, SM64>>>(
            Xh, Xl, w1h, w1l, b1 + l*MLPD, nullptr, nullptr, Hh, Hl, NROWS, MLPD, DD);
        hgemm3_kernel<64,4,2,0,1,1,1><<<dim3(DD/64, NROWS/128), 256, SM64>>>(
            Hh, Hl, w2h, w2l, b2 + l*DD, X, X, Xh, Xl, NROWS, DD, MLPD);
    }

    ln_kernel<<<NROWS, 256>>>(X, lnf_g, lnf_b, out);
}